// round 1
// baseline (speedup 1.0000x reference)
#include <cuda_runtime.h>
#include <cstdint>

#define BH      16
#define LSEQ    4096
#define DIM     128
#define CHK     32
#define DV      16
#define NSLICE  8
#define NCHUNK  (LSEQ / CHK)

struct SM {
    float Q[CHK][DIM + 1];   // normalized q chunk
    float K[CHK][DIM + 1];   // normalized k chunk
    float W[CHK][DIM + 1];   // rhs k_beta -> w after substitution
    float T[CHK][CHK + 1];   // strict-lower A*beta
    float At[CHK][CHK + 1];  // causal local attention
    float U[CHK][DV + 1];    // rhs v*beta -> u -> u_adj
    float O[CHK][DV + 1];    // q @ S partial
    float S[DIM][DV + 1];    // running state slice
    float beta[CHK];
    float rq[CHK];
    float rk[CHK];
};

extern "C" __global__ void __launch_bounds__(256, 1)
deltanet_kernel(const float* __restrict__ q, const float* __restrict__ k,
                const float* __restrict__ v, const float* __restrict__ beta,
                float* __restrict__ out, float* __restrict__ sfinal, int write_s)
{
    extern __shared__ char smraw[];
    SM& sm = *reinterpret_cast<SM*>(smraw);

    const int bh   = blockIdx.x;   // 0..15
    const int sl   = blockIdx.y;   // 0..7  (d_v slice)
    const int tid  = threadIdx.x;
    const int lane = tid & 31;
    const int warp = tid >> 5;

    const float* qb = q    + (size_t)bh * LSEQ * DIM;
    const float* kb = k    + (size_t)bh * LSEQ * DIM;
    const float* vb = v    + (size_t)bh * LSEQ * DIM + sl * DV;
    const float* bb = beta + (size_t)bh * LSEQ;
    float*       ob = out  + (size_t)bh * LSEQ * DIM + sl * DV;

    // zero state
    for (int idx = tid; idx < DIM * DV; idx += 256)
        sm.S[idx >> 4][idx & 15] = 0.f;
    __syncthreads();

    for (int ch = 0; ch < NCHUNK; ch++) {
        const float* qc = qb + (size_t)ch * CHK * DIM;
        const float* kc = kb + (size_t)ch * CHK * DIM;

        // ---- phase 1: load raw q,k, beta, v-slice ----
        for (int idx = tid; idx < CHK * DIM; idx += 256) {
            int r = idx >> 7, c = idx & 127;
            sm.Q[r][c] = qc[idx];
            sm.K[r][c] = kc[idx];
        }
        if (tid < CHK) sm.beta[tid] = bb[ch * CHK + tid];
        for (int idx = tid; idx < CHK * DV; idx += 256) {
            int r = idx >> 4, j = idx & 15;
            sm.U[r][j] = vb[(size_t)(ch * CHK + r) * DIM + j];
        }
        __syncthreads();

        // ---- phase 2: row L2 norms (warp w -> rows 4w..4w+3, 8 lanes/row) ----
        {
            int row = warp * 4 + (lane >> 3);
            int sub = lane & 7;
            float sq = 0.f, sk2 = 0.f;
            #pragma unroll
            for (int t = 0; t < 16; t++) {
                float a  = sm.Q[row][sub + 8 * t]; sq  += a  * a;
                float b2 = sm.K[row][sub + 8 * t]; sk2 += b2 * b2;
            }
            #pragma unroll
            for (int off = 4; off >= 1; off >>= 1) {
                sq  += __shfl_xor_sync(0xffffffffu, sq,  off);
                sk2 += __shfl_xor_sync(0xffffffffu, sk2, off);
            }
            if (sub == 0) { sm.rq[row] = rsqrtf(sq); sm.rk[row] = rsqrtf(sk2); }
        }
        __syncthreads();

        // ---- phase 3: scale q,k; build rhs W = k_norm*beta, U *= beta ----
        for (int idx = tid; idx < CHK * DIM; idx += 256) {
            int r = idx >> 7, c = idx & 127;
            float kn = sm.K[r][c] * sm.rk[r];
            sm.Q[r][c] *= sm.rq[r];
            sm.K[r][c] = kn;
            sm.W[r][c] = kn * sm.beta[r];
        }
        for (int idx = tid; idx < CHK * DV; idx += 256) {
            int r = idx >> 4, j = idx & 15;
            sm.U[r][j] *= sm.beta[r];
        }
        __syncthreads();

        // ---- phase 4: T strict-lower = beta_i * (k_i . k_j)  (2x2 tiles) ----
        {
            int a = tid >> 4, b = tid & 15;
            int i0 = 2 * a, j0 = 2 * b;
            float d00 = 0, d01 = 0, d10 = 0, d11 = 0;
            #pragma unroll 4
            for (int c = 0; c < DIM; c++) {
                float ki0 = sm.K[i0][c],     ki1 = sm.K[i0 + 1][c];
                float kj0 = sm.K[j0][c],     kj1 = sm.K[j0 + 1][c];
                d00 += ki0 * kj0; d01 += ki0 * kj1;
                d10 += ki1 * kj0; d11 += ki1 * kj1;
            }
            sm.T[i0][j0]         = (i0 > j0)         ? sm.beta[i0]     * d00 : 0.f;
            sm.T[i0][j0 + 1]     = (i0 > j0 + 1)     ? sm.beta[i0]     * d01 : 0.f;
            sm.T[i0 + 1][j0]     = (i0 + 1 > j0)     ? sm.beta[i0 + 1] * d10 : 0.f;
            sm.T[i0 + 1][j0 + 1] = (i0 + 1 > j0 + 1) ? sm.beta[i0 + 1] * d11 : 0.f;
        }
        __syncthreads();

        // ---- phase 5: forward substitution, solve T x = rhs per column ----
        // unit-lower T => x[i] = rhs[i] - sum_{m<i} T[i][m] x[m]; all in regs
        if (tid < DIM + DV) {
            float x[CHK];
            if (tid < DIM) {
                #pragma unroll
                for (int i = 0; i < CHK; i++) x[i] = sm.W[i][tid];
            } else {
                #pragma unroll
                for (int i = 0; i < CHK; i++) x[i] = sm.U[i][tid - DIM];
            }
            #pragma unroll
            for (int i = 1; i < CHK; i++) {
                float acc = x[i];
                #pragma unroll
                for (int m = 0; m < i; m++) acc -= sm.T[i][m] * x[m];
                x[i] = acc;
            }
            if (tid < DIM) {
                #pragma unroll
                for (int i = 0; i < CHK; i++) sm.W[i][tid] = x[i];
            } else {
                #pragma unroll
                for (int i = 0; i < CHK; i++) sm.U[i][tid - DIM] = x[i];
            }
        }
        __syncthreads();

        // ---- phase 6: causal attn (2x2 tiles) + O = q @ S ----
        {
            int a = tid >> 4, b = tid & 15;
            int i0 = 2 * a, j0 = 2 * b;
            float d00 = 0, d01 = 0, d10 = 0, d11 = 0;
            #pragma unroll 4
            for (int c = 0; c < DIM; c++) {
                float qi0 = sm.Q[i0][c],     qi1 = sm.Q[i0 + 1][c];
                float kj0 = sm.K[j0][c],     kj1 = sm.K[j0 + 1][c];
                d00 += qi0 * kj0; d01 += qi0 * kj1;
                d10 += qi1 * kj0; d11 += qi1 * kj1;
            }
            sm.At[i0][j0]         = (i0 >= j0)         ? d00 : 0.f;
            sm.At[i0][j0 + 1]     = (i0 >= j0 + 1)     ? d01 : 0.f;
            sm.At[i0 + 1][j0]     = (i0 + 1 >= j0)     ? d10 : 0.f;
            sm.At[i0 + 1][j0 + 1] = (i0 + 1 >= j0 + 1) ? d11 : 0.f;

            int i = tid >> 3, bj = tid & 7;
            float o0 = 0, o1 = 0;
            #pragma unroll 4
            for (int c = 0; c < DIM; c++) {
                float qv = sm.Q[i][c];
                o0 += qv * sm.S[c][bj];
                o1 += qv * sm.S[c][bj + 8];
            }
            sm.O[i][bj] = o0; sm.O[i][bj + 8] = o1;
        }
        __syncthreads();

        // ---- phase 7: u_adj = u - w @ S ----
        {
            int i = tid >> 3, bj = tid & 7;
            float a0 = 0, a1 = 0;
            #pragma unroll 4
            for (int c = 0; c < DIM; c++) {
                float wv = sm.W[i][c];
                a0 += wv * sm.S[c][bj];
                a1 += wv * sm.S[c][bj + 8];
            }
            sm.U[i][bj]     -= a0;
            sm.U[i][bj + 8] -= a1;
        }
        __syncthreads();

        // ---- phase 8: o = O + At @ u_adj  (write out); S += k^T @ u_adj ----
        {
            int i = tid >> 3, bj = tid & 7;
            float o0 = sm.O[i][bj], o1 = sm.O[i][bj + 8];
            #pragma unroll
            for (int f = 0; f < CHK; f++) {
                float av = sm.At[i][f];
                o0 += av * sm.U[f][bj];
                o1 += av * sm.U[f][bj + 8];
            }
            ob[(size_t)(ch * CHK + i) * DIM + bj]     = o0;
            ob[(size_t)(ch * CHK + i) * DIM + bj + 8] = o1;

            // S update: thread owns dk rows 4*i..4*i+3, cols bj, bj+8
            float acc[4][2] = {};
            #pragma unroll
            for (int r = 0; r < CHK; r++) {
                float u0 = sm.U[r][bj], u1 = sm.U[r][bj + 8];
                #pragma unroll
                for (int t = 0; t < 4; t++) {
                    float kv = sm.K[r][4 * i + t];
                    acc[t][0] += kv * u0; acc[t][1] += kv * u1;
                }
            }
            #pragma unroll
            for (int t = 0; t < 4; t++) {
                sm.S[4 * i + t][bj]     += acc[t][0];
                sm.S[4 * i + t][bj + 8] += acc[t][1];
            }
        }
        __syncthreads();
    }

    // ---- final state write ----
    if (write_s) {
        float* sf = sfinal + (size_t)bh * DIM * DIM + sl * DV;
        for (int idx = tid; idx < DIM * DV; idx += 256) {
            int r = idx >> 4, j = idx & 15;
            sf[(size_t)r * DIM + j] = sm.S[r][j];
        }
    }
}

extern "C" void kernel_launch(void* const* d_in, const int* in_sizes, int n_in,
                              void* d_out, int out_size) {
    const float* q    = (const float*)d_in[0];
    const float* k    = (const float*)d_in[1];
    const float* v    = (const float*)d_in[2];
    const float* beta = (const float*)d_in[3];
    float* out = (float*)d_out;

    const int out_elems = BH * LSEQ * DIM;           // 8388608
    const int s_elems   = BH * DIM * DIM;            // 262144
    int write_s = (out_size >= out_elems + s_elems) ? 1 : 0;
    float* sf = out + out_elems;

    cudaFuncSetAttribute(deltanet_kernel,
                         cudaFuncAttributeMaxDynamicSharedMemorySize,
                         (int)sizeof(SM));
    dim3 grid(BH, NSLICE);
    deltanet_kernel<<<grid, 256, sizeof(SM)>>>(q, k, v, beta, out, sf, write_s);
}

// round 4
// speedup vs baseline: 2.5084x; 2.5084x over previous
#include <cuda_runtime.h>
#include <cstdint>

#define BH      16
#define LSEQ    4096
#define DIM     128
#define CHK     32
#define DV      16
#define NSLICE  8
#define NCHUNK  (LSEQ / CHK)
#define PD      132   // padded row length (floats), 528B = 16B-aligned

// ---- scratch (device globals; allocation-free) ----
__device__ float g_QN[(size_t)BH * LSEQ * DIM];
__device__ float g_KN[(size_t)BH * LSEQ * DIM];
__device__ float g_W [(size_t)BH * LSEQ * DIM];
__device__ float g_U [(size_t)BH * LSEQ * DIM];
__device__ float g_AT[(size_t)BH * NCHUNK * CHK * CHK];

// ---- cp.async helpers ----
__device__ __forceinline__ void cp16(void* smem_dst, const void* gmem_src) {
    uint32_t s = (uint32_t)__cvta_generic_to_shared(smem_dst);
    asm volatile("cp.async.cg.shared.global [%0], [%1], 16;\n" :: "r"(s), "l"(gmem_src));
}
__device__ __forceinline__ void cp_commit() {
    asm volatile("cp.async.commit_group;\n" ::: "memory");
}
__device__ __forceinline__ void cp_wait_all() {
    asm volatile("cp.async.wait_group 0;\n" ::: "memory");
}

// ============================================================
// Kernel 1: fully parallel per-(bh,chunk) preparation
//   qn, kn (l2-normalized), w = T^-1 k_beta, u = T^-1 v_beta,
//   At = causal(qn @ kn^T)
// ============================================================
struct SM1 {
    float Qn[CHK][PD];
    float Kn[CHK][PD];
    float Kb[CHK][PD];
    float Vb[CHK][PD];
    float T [CHK][CHK + 1];
    float beta[CHK], rq[CHK], rk[CHK];
};

extern "C" __global__ void __launch_bounds__(256)
k1_prepare(const float* __restrict__ q, const float* __restrict__ k,
           const float* __restrict__ v, const float* __restrict__ beta)
{
    extern __shared__ __align__(16) char smraw1[];
    SM1& sm = *reinterpret_cast<SM1*>(smraw1);
    const int ch = blockIdx.x, bh = blockIdx.y;
    const int tid = threadIdx.x, lane = tid & 31, warp = tid >> 5;
    const size_t base = ((size_t)bh * LSEQ + (size_t)ch * CHK) * DIM;

    for (int idx = tid; idx < CHK * DIM; idx += 256) {
        int r = idx >> 7, c = idx & 127;
        sm.Qn[r][c] = q[base + idx];
        sm.Kn[r][c] = k[base + idx];
        sm.Vb[r][c] = v[base + idx];
    }
    if (tid < CHK) sm.beta[tid] = beta[(size_t)bh * LSEQ + ch * CHK + tid];
    __syncthreads();

    { // row L2 norms: warp w -> rows 4w..4w+3, 8 lanes per row
        int row = warp * 4 + (lane >> 3), sub = lane & 7;
        float sq = 0.f, sk = 0.f;
        #pragma unroll
        for (int t = 0; t < 16; t++) {
            float a  = sm.Qn[row][sub + 8 * t]; sq += a * a;
            float b2 = sm.Kn[row][sub + 8 * t]; sk += b2 * b2;
        }
        #pragma unroll
        for (int off = 4; off >= 1; off >>= 1) {
            sq += __shfl_xor_sync(0xffffffffu, sq, off);
            sk += __shfl_xor_sync(0xffffffffu, sk, off);
        }
        if (sub == 0) { sm.rq[row] = rsqrtf(sq); sm.rk[row] = rsqrtf(sk); }
    }
    __syncthreads();

    for (int idx = tid; idx < CHK * DIM; idx += 256) {
        int r = idx >> 7, c = idx & 127;
        float bt = sm.beta[r];
        float qn = sm.Qn[r][c] * sm.rq[r];
        float kn = sm.Kn[r][c] * sm.rk[r];
        sm.Qn[r][c] = qn;
        sm.Kn[r][c] = kn;
        sm.Kb[r][c] = kn * bt;
        sm.Vb[r][c] *= bt;
        g_QN[base + idx] = qn;
        g_KN[base + idx] = kn;
    }
    __syncthreads();

    { // T (strict lower, kb.kn) and At (causal, qn.kn) with 2x2 tiles, float4 on c
        int a = tid >> 4, b = tid & 15;
        int i0 = 2 * a, j0 = 2 * b;
        float t00 = 0, t01 = 0, t10 = 0, t11 = 0;
        float a00 = 0, a01 = 0, a10 = 0, a11 = 0;
        #pragma unroll 4
        for (int c4 = 0; c4 < DIM; c4 += 4) {
            float4 kb0 = *(const float4*)&sm.Kb[i0][c4];
            float4 kb1 = *(const float4*)&sm.Kb[i0 + 1][c4];
            float4 qn0 = *(const float4*)&sm.Qn[i0][c4];
            float4 qn1 = *(const float4*)&sm.Qn[i0 + 1][c4];
            float4 kn0 = *(const float4*)&sm.Kn[j0][c4];
            float4 kn1 = *(const float4*)&sm.Kn[j0 + 1][c4];
            t00 += kb0.x*kn0.x + kb0.y*kn0.y + kb0.z*kn0.z + kb0.w*kn0.w;
            t01 += kb0.x*kn1.x + kb0.y*kn1.y + kb0.z*kn1.z + kb0.w*kn1.w;
            t10 += kb1.x*kn0.x + kb1.y*kn0.y + kb1.z*kn0.z + kb1.w*kn0.w;
            t11 += kb1.x*kn1.x + kb1.y*kn1.y + kb1.z*kn1.z + kb1.w*kn1.w;
            a00 += qn0.x*kn0.x + qn0.y*kn0.y + qn0.z*kn0.z + qn0.w*kn0.w;
            a01 += qn0.x*kn1.x + qn0.y*kn1.y + qn0.z*kn1.z + qn0.w*kn1.w;
            a10 += qn1.x*kn0.x + qn1.y*kn0.y + qn1.z*kn0.z + qn1.w*kn0.w;
            a11 += qn1.x*kn1.x + qn1.y*kn1.y + qn1.z*kn1.z + qn1.w*kn1.w;
        }
        sm.T[i0][j0]         = (i0 > j0)         ? t00 : 0.f;
        sm.T[i0][j0 + 1]     = (i0 > j0 + 1)     ? t01 : 0.f;
        sm.T[i0 + 1][j0]     = (i0 + 1 > j0)     ? t10 : 0.f;
        sm.T[i0 + 1][j0 + 1] = (i0 + 1 > j0 + 1) ? t11 : 0.f;
        float* atg = g_AT + (size_t)(bh * NCHUNK + ch) * CHK * CHK;
        atg[i0 * CHK + j0]           = (i0 >= j0)         ? a00 : 0.f;
        atg[i0 * CHK + j0 + 1]       = (i0 >= j0 + 1)     ? a01 : 0.f;
        atg[(i0 + 1) * CHK + j0]     = (i0 + 1 >= j0)     ? a10 : 0.f;
        atg[(i0 + 1) * CHK + j0 + 1] = (i0 + 1 >= j0 + 1) ? a11 : 0.f;
    }
    __syncthreads();

    { // forward substitution: 256 threads = 256 rhs columns [kb | vb]
        const bool left = tid < DIM;
        const int col = left ? tid : tid - DIM;
        float x[CHK];
        #pragma unroll
        for (int i = 0; i < CHK; i++) x[i] = left ? sm.Kb[i][col] : sm.Vb[i][col];
        #pragma unroll
        for (int i = 1; i < CHK; i++) {
            float acc = x[i];
            #pragma unroll
            for (int m = 0; m < i; m++) acc -= sm.T[i][m] * x[m];
            x[i] = acc;
        }
        float* dst = (left ? g_W : g_U) + base + col;
        #pragma unroll
        for (int i = 0; i < CHK; i++) dst[(size_t)i * DIM] = x[i];
    }
}

// ============================================================
// Kernel 2: sequential scan per (bh, dv-slice), cp.async double-buffered
// ============================================================
struct Buf {
    float Qn [CHK][PD];
    float Kn [CHK][PD];
    float Wv [CHK][PD];
    float Ub [CHK][DV];
    float Atb[CHK][CHK];
};
struct SM2 {
    float St[DV][PD];      // S^T slice: [j][c]
    float UA[CHK][DV];
    Buf   buf[2];
};

__device__ __forceinline__ void load_buf(Buf& B, int bh, int ch, int sl, int tid)
{
    const size_t base = ((size_t)bh * LSEQ + (size_t)ch * CHK) * DIM;
    const float* qs = g_QN + base;
    const float* ks = g_KN + base;
    const float* ws = g_W  + base;
    const float* us = g_U  + base + sl * DV;
    const float* ats = g_AT + (size_t)(bh * NCHUNK + ch) * CHK * CHK;

    #pragma unroll
    for (int t = tid; t < 1024; t += 256) {
        int r = t >> 5, c4 = (t & 31) * 4;
        cp16(&B.Qn[r][c4], qs + r * DIM + c4);
        cp16(&B.Kn[r][c4], ks + r * DIM + c4);
        cp16(&B.Wv[r][c4], ws + r * DIM + c4);
    }
    if (tid < 128) {
        int r = tid >> 2, c4 = (tid & 3) * 4;
        cp16(&B.Ub[r][c4], us + r * DIM + c4);
    }
    {
        int r = tid >> 3, c4 = (tid & 7) * 4;
        cp16(&B.Atb[r][c4], ats + r * CHK + c4);
    }
}

extern "C" __global__ void __launch_bounds__(256, 1)
k2_scan(float* __restrict__ out, float* __restrict__ sfinal, int write_s)
{
    extern __shared__ __align__(16) char smraw2[];
    SM2& sm = *reinterpret_cast<SM2*>(smraw2);
    const int bh = blockIdx.x, sl = blockIdx.y;
    const int tid = threadIdx.x;

    float* ob = out + (size_t)bh * LSEQ * DIM + sl * DV;

    for (int idx = tid; idx < DV * DIM; idx += 256)
        sm.St[idx >> 7][idx & 127] = 0.f;

    load_buf(sm.buf[0], bh, 0, sl, tid);
    cp_commit();

    const int i  = tid >> 3, jj = tid & 7;       // out-tile layout
    const int js = tid >> 4, cg = tid & 15;      // S-update layout
    const int c0 = cg * 8;

    for (int ch = 0; ch < NCHUNK; ch++) {
        cp_wait_all();
        __syncthreads();
        if (ch + 1 < NCHUNK) {
            load_buf(sm.buf[(ch + 1) & 1], bh, ch + 1, sl, tid);
            cp_commit();
        }
        const Buf& B = sm.buf[ch & 1];

        // ---- phase A: O = qn@S, UA = u - w@S  (S^T float4 inner) ----
        float O0 = 0.f, O1 = 0.f, A0 = 0.f, A1 = 0.f;
        #pragma unroll 8
        for (int c4 = 0; c4 < DIM; c4 += 4) {
            float4 qv = *(const float4*)&B.Qn[i][c4];
            float4 wv = *(const float4*)&B.Wv[i][c4];
            float4 s0 = *(const float4*)&sm.St[jj][c4];
            float4 s1 = *(const float4*)&sm.St[jj + 8][c4];
            O0 += qv.x*s0.x + qv.y*s0.y + qv.z*s0.z + qv.w*s0.w;
            O1 += qv.x*s1.x + qv.y*s1.y + qv.z*s1.z + qv.w*s1.w;
            A0 += wv.x*s0.x + wv.y*s0.y + wv.z*s0.z + wv.w*s0.w;
            A1 += wv.x*s1.x + wv.y*s1.y + wv.z*s1.z + wv.w*s1.w;
        }
        sm.UA[i][jj]     = B.Ub[i][jj]     - A0;
        sm.UA[i][jj + 8] = B.Ub[i][jj + 8] - A1;
        __syncthreads();

        // ---- phase C1: out = O + At @ UA ----
        float o0 = O0, o1 = O1;
        #pragma unroll
        for (int f = 0; f < CHK; f++) {
            float av = B.Atb[i][f];
            o0 += av * sm.UA[f][jj];
            o1 += av * sm.UA[f][jj + 8];
        }
        ob[(size_t)(ch * CHK + i) * DIM + jj]     = o0;
        ob[(size_t)(ch * CHK + i) * DIM + jj + 8] = o1;

        // ---- phase C2: S^T[js][c0..c0+7] += sum_r UA[r][js] * kn[r][c] ----
        float4 acc0 = make_float4(0.f, 0.f, 0.f, 0.f);
        float4 acc1 = make_float4(0.f, 0.f, 0.f, 0.f);
        #pragma unroll 4
        for (int r = 0; r < CHK; r++) {
            float uv = sm.UA[r][js];
            float4 k0 = *(const float4*)&B.Kn[r][c0];
            float4 k1 = *(const float4*)&B.Kn[r][c0 + 4];
            acc0.x += uv * k0.x; acc0.y += uv * k0.y;
            acc0.z += uv * k0.z; acc0.w += uv * k0.w;
            acc1.x += uv * k1.x; acc1.y += uv * k1.y;
            acc1.z += uv * k1.z; acc1.w += uv * k1.w;
        }
        {
            float4* p0 = (float4*)&sm.St[js][c0];
            float4* p1 = (float4*)&sm.St[js][c0 + 4];
            float4 v0 = *p0, v1 = *p1;
            v0.x += acc0.x; v0.y += acc0.y; v0.z += acc0.z; v0.w += acc0.w;
            v1.x += acc1.x; v1.y += acc1.y; v1.z += acc1.z; v1.w += acc1.w;
            *p0 = v0; *p1 = v1;
        }
        // loop-top barrier (after cp_wait_all) separates C2's St writes
        // from next iteration's phase-A St reads.
    }

    if (write_s) {
        __syncthreads();
        float* sf = sfinal + (size_t)bh * DIM * DIM + sl * DV;
        for (int idx = tid; idx < DIM * DV; idx += 256) {
            int c = idx >> 4, j = idx & 15;
            sf[(size_t)c * DIM + j] = sm.St[j][c];
        }
    }
}

// ============================================================
extern "C" void kernel_launch(void* const* d_in, const int* in_sizes, int n_in,
                              void* d_out, int out_size) {
    const float* q    = (const float*)d_in[0];
    const float* k    = (const float*)d_in[1];
    const float* v    = (const float*)d_in[2];
    const float* beta = (const float*)d_in[3];
    float* out = (float*)d_out;

    const int out_elems = BH * LSEQ * DIM;
    const int s_elems   = BH * DIM * DIM;
    int write_s = (out_size >= out_elems + s_elems) ? 1 : 0;
    float* sf = out + out_elems;

    static bool attr_done = false;
    if (!attr_done) {
        cudaFuncSetAttribute(k1_prepare, cudaFuncAttributeMaxDynamicSharedMemorySize,
                             (int)sizeof(SM1));
        cudaFuncSetAttribute(k2_scan, cudaFuncAttributeMaxDynamicSharedMemorySize,
                             (int)sizeof(SM2));
        attr_done = true;
    }

    dim3 g1(NCHUNK, BH);
    k1_prepare<<<g1, 256, sizeof(SM1)>>>(q, k, v, beta);

    dim3 g2(BH, NSLICE);
    k2_scan<<<g2, 256, sizeof(SM2)>>>(out, sf, write_s);
}

// round 5
// speedup vs baseline: 3.0207x; 1.2042x over previous
#include <cuda_runtime.h>
#include <cstdint>

#define BH      16
#define LSEQ    4096
#define DIM     128
#define CHK     32
#define DV      16
#define NSLICE  8
#define NCHUNK  (LSEQ / CHK)
#define PD      132   // padded row length (floats), 528B, 16B-aligned
#define THR2    512

// ---- scratch (device globals; allocation-free) ----
__device__ float g_QN[(size_t)BH * LSEQ * DIM];
__device__ float g_KN[(size_t)BH * LSEQ * DIM];
__device__ float g_W [(size_t)BH * LSEQ * DIM];
__device__ float g_U [(size_t)BH * LSEQ * DIM];
__device__ float g_AT[(size_t)BH * NCHUNK * CHK * CHK];

// ---- packed f32x2 helpers ----
__device__ __forceinline__ unsigned long long ffma2(unsigned long long a,
                                                    unsigned long long b,
                                                    unsigned long long c) {
    unsigned long long d;
    asm("fma.rn.f32x2 %0, %1, %2, %3;" : "=l"(d) : "l"(a), "l"(b), "l"(c));
    return d;
}
__device__ __forceinline__ unsigned long long fadd2(unsigned long long a,
                                                    unsigned long long b) {
    unsigned long long d;
    asm("add.rn.f32x2 %0, %1, %2;" : "=l"(d) : "l"(a), "l"(b));
    return d;
}
__device__ __forceinline__ unsigned long long pack2(float v) {
    unsigned long long d;
    asm("mov.b64 %0, {%1, %1};" : "=l"(d) : "f"(v));
    return d;
}
__device__ __forceinline__ float hadd2(unsigned long long v) {
    float lo, hi;
    asm("mov.b64 {%0, %1}, %2;" : "=f"(lo), "=f"(hi) : "l"(v));
    return lo + hi;
}

// ---- cp.async helpers ----
__device__ __forceinline__ void cp16(void* smem_dst, const void* gmem_src) {
    uint32_t s = (uint32_t)__cvta_generic_to_shared(smem_dst);
    asm volatile("cp.async.cg.shared.global [%0], [%1], 16;\n" :: "r"(s), "l"(gmem_src));
}
__device__ __forceinline__ void cp_commit() {
    asm volatile("cp.async.commit_group;\n" ::: "memory");
}
__device__ __forceinline__ void cp_wait_all() {
    asm volatile("cp.async.wait_group 0;\n" ::: "memory");
}

// ============================================================
// Kernel 1: fully parallel per-(bh,chunk) preparation
// ============================================================
struct SM1 {
    float Qn[CHK][PD];
    float Kn[CHK][PD];
    float Kb[CHK][PD];
    float Vb[CHK][PD];
    float T [CHK][CHK + 1];
    float beta[CHK], rq[CHK], rk[CHK];
};

extern "C" __global__ void __launch_bounds__(256)
k1_prepare(const float* __restrict__ q, const float* __restrict__ k,
           const float* __restrict__ v, const float* __restrict__ beta)
{
    extern __shared__ __align__(16) char smraw1[];
    SM1& sm = *reinterpret_cast<SM1*>(smraw1);
    const int ch = blockIdx.x, bh = blockIdx.y;
    const int tid = threadIdx.x, lane = tid & 31, warp = tid >> 5;
    const size_t base = ((size_t)bh * LSEQ + (size_t)ch * CHK) * DIM;

    for (int idx = tid; idx < CHK * DIM; idx += 256) {
        int r = idx >> 7, c = idx & 127;
        sm.Qn[r][c] = q[base + idx];
        sm.Kn[r][c] = k[base + idx];
        sm.Vb[r][c] = v[base + idx];
    }
    if (tid < CHK) sm.beta[tid] = beta[(size_t)bh * LSEQ + ch * CHK + tid];
    __syncthreads();

    { // row L2 norms
        int row = warp * 4 + (lane >> 3), sub = lane & 7;
        float sq = 0.f, sk = 0.f;
        #pragma unroll
        for (int t = 0; t < 16; t++) {
            float a  = sm.Qn[row][sub + 8 * t]; sq += a * a;
            float b2 = sm.Kn[row][sub + 8 * t]; sk += b2 * b2;
        }
        #pragma unroll
        for (int off = 4; off >= 1; off >>= 1) {
            sq += __shfl_xor_sync(0xffffffffu, sq, off);
            sk += __shfl_xor_sync(0xffffffffu, sk, off);
        }
        if (sub == 0) { sm.rq[row] = rsqrtf(sq); sm.rk[row] = rsqrtf(sk); }
    }
    __syncthreads();

    for (int idx = tid; idx < CHK * DIM; idx += 256) {
        int r = idx >> 7, c = idx & 127;
        float bt = sm.beta[r];
        float qn = sm.Qn[r][c] * sm.rq[r];
        float kn = sm.Kn[r][c] * sm.rk[r];
        sm.Qn[r][c] = qn;
        sm.Kn[r][c] = kn;
        sm.Kb[r][c] = kn * bt;
        sm.Vb[r][c] *= bt;
        g_QN[base + idx] = qn;
        g_KN[base + idx] = kn;
    }
    __syncthreads();

    { // T (strict lower, kb.kn) and At (causal, qn.kn), 2x2 tiles, f32x2 math
        int a = tid >> 4, b = tid & 15;
        int i0 = 2 * a, j0 = 2 * b;
        unsigned long long t00 = 0, t01 = 0, t10 = 0, t11 = 0;
        unsigned long long a00 = 0, a01 = 0, a10 = 0, a11 = 0;
        #pragma unroll 8
        for (int c4 = 0; c4 < DIM; c4 += 4) {
            ulonglong2 kb0 = *(const ulonglong2*)&sm.Kb[i0][c4];
            ulonglong2 kb1 = *(const ulonglong2*)&sm.Kb[i0 + 1][c4];
            ulonglong2 qn0 = *(const ulonglong2*)&sm.Qn[i0][c4];
            ulonglong2 qn1 = *(const ulonglong2*)&sm.Qn[i0 + 1][c4];
            ulonglong2 kn0 = *(const ulonglong2*)&sm.Kn[j0][c4];
            ulonglong2 kn1 = *(const ulonglong2*)&sm.Kn[j0 + 1][c4];
            t00 = ffma2(kb0.x, kn0.x, t00); t00 = ffma2(kb0.y, kn0.y, t00);
            t01 = ffma2(kb0.x, kn1.x, t01); t01 = ffma2(kb0.y, kn1.y, t01);
            t10 = ffma2(kb1.x, kn0.x, t10); t10 = ffma2(kb1.y, kn0.y, t10);
            t11 = ffma2(kb1.x, kn1.x, t11); t11 = ffma2(kb1.y, kn1.y, t11);
            a00 = ffma2(qn0.x, kn0.x, a00); a00 = ffma2(qn0.y, kn0.y, a00);
            a01 = ffma2(qn0.x, kn1.x, a01); a01 = ffma2(qn0.y, kn1.y, a01);
            a10 = ffma2(qn1.x, kn0.x, a10); a10 = ffma2(qn1.y, kn0.y, a10);
            a11 = ffma2(qn1.x, kn1.x, a11); a11 = ffma2(qn1.y, kn1.y, a11);
        }
        sm.T[i0][j0]         = (i0 > j0)         ? hadd2(t00) : 0.f;
        sm.T[i0][j0 + 1]     = (i0 > j0 + 1)     ? hadd2(t01) : 0.f;
        sm.T[i0 + 1][j0]     = (i0 + 1 > j0)     ? hadd2(t10) : 0.f;
        sm.T[i0 + 1][j0 + 1] = (i0 + 1 > j0 + 1) ? hadd2(t11) : 0.f;
        float* atg = g_AT + (size_t)(bh * NCHUNK + ch) * CHK * CHK;
        atg[i0 * CHK + j0]           = (i0 >= j0)         ? hadd2(a00) : 0.f;
        atg[i0 * CHK + j0 + 1]       = (i0 >= j0 + 1)     ? hadd2(a01) : 0.f;
        atg[(i0 + 1) * CHK + j0]     = (i0 + 1 >= j0)     ? hadd2(a10) : 0.f;
        atg[(i0 + 1) * CHK + j0 + 1] = (i0 + 1 >= j0 + 1) ? hadd2(a11) : 0.f;
    }
    __syncthreads();

    { // forward substitution: 256 threads = 256 rhs columns [kb | vb]
        const bool left = tid < DIM;
        const int col = left ? tid : tid - DIM;
        float x[CHK];
        #pragma unroll
        for (int i = 0; i < CHK; i++) x[i] = left ? sm.Kb[i][col] : sm.Vb[i][col];
        #pragma unroll
        for (int i = 1; i < CHK; i++) {
            float acc = x[i];
            #pragma unroll
            for (int m = 0; m < i; m++) acc -= sm.T[i][m] * x[m];
            x[i] = acc;
        }
        float* dst = (left ? g_W : g_U) + base + col;
        #pragma unroll
        for (int i = 0; i < CHK; i++) dst[(size_t)i * DIM] = x[i];
    }
}

// ============================================================
// Kernel 2: sequential scan, 512 threads, f32x2, double-buffered
// ============================================================
struct Buf {
    float Qn [CHK][PD];
    float Kn [CHK][PD];
    float Wv [CHK][PD];
    float Ub [CHK][DV];
    float Atb[CHK][CHK];
};
struct SM2 {
    float St [DV][PD];     // S^T slice: [j][c]
    float UAT[DV][36];     // (u - w@S)^T: [j][i], stride 36 (16B-aligned rows)
    Buf   buf[2];
};

__device__ __forceinline__ void load_buf(Buf& B, int bh, int ch, int sl, int tid)
{
    const size_t base = ((size_t)bh * LSEQ + (size_t)ch * CHK) * DIM;
    const float* qs  = g_QN + base;
    const float* ks  = g_KN + base;
    const float* ws  = g_W  + base;
    const float* us  = g_U  + base + sl * DV;
    const float* ats = g_AT + (size_t)(bh * NCHUNK + ch) * CHK * CHK;

    #pragma unroll
    for (int t = tid; t < 1024; t += THR2) {
        int r = t >> 5, c4 = (t & 31) * 4;
        cp16(&B.Qn[r][c4], qs + r * DIM + c4);
        cp16(&B.Kn[r][c4], ks + r * DIM + c4);
        cp16(&B.Wv[r][c4], ws + r * DIM + c4);
    }
    if (tid < 128) {
        int r = tid >> 2, c4 = (tid & 3) * 4;
        cp16(&B.Ub[r][c4], us + r * DIM + c4);
    }
    if (tid < 256) {
        int r = tid >> 3, c4 = (tid & 7) * 4;
        cp16(&B.Atb[r][c4], ats + r * CHK + c4);
    }
}

extern "C" __global__ void __launch_bounds__(THR2, 1)
k2_scan(float* __restrict__ out, float* __restrict__ sfinal, int write_s)
{
    extern __shared__ __align__(16) char smraw2[];
    SM2& sm = *reinterpret_cast<SM2*>(smraw2);
    const int bh = blockIdx.x, sl = blockIdx.y;
    const int tid = threadIdx.x;

    float* ob = out + (size_t)bh * LSEQ * DIM + sl * DV;

    for (int idx = tid; idx < DV * DIM; idx += THR2)
        sm.St[idx >> 7][idx & 127] = 0.f;

    load_buf(sm.buf[0], bh, 0, sl, tid);
    cp_commit();

    const int i  = tid >> 4;        // 0..31 (phase A / C1 row)
    const int j  = tid & 15;        // 0..15 (dv col)
    const int jsg = tid >> 5;       // 0..7 valid (C2, 2 js rows)
    const int cg  = tid & 31;       // 0..31 (C2 c-group)
    const int c0  = cg * 4;

    for (int ch = 0; ch < NCHUNK; ch++) {
        cp_wait_all();
        __syncthreads();
        if (ch + 1 < NCHUNK) {
            load_buf(sm.buf[(ch + 1) & 1], bh, ch + 1, sl, tid);
            cp_commit();
        }
        const Buf& B = sm.buf[ch & 1];

        // ---- phase A: O = qn@S, A = w@S, UAT[j][i] = u - A ----
        unsigned long long O2 = 0, A2 = 0;
        #pragma unroll 8
        for (int c4 = 0; c4 < DIM; c4 += 4) {
            ulonglong2 q2 = *(const ulonglong2*)&B.Qn[i][c4];
            ulonglong2 w2 = *(const ulonglong2*)&B.Wv[i][c4];
            ulonglong2 s2 = *(const ulonglong2*)&sm.St[j][c4];
            O2 = ffma2(q2.x, s2.x, O2); O2 = ffma2(q2.y, s2.y, O2);
            A2 = ffma2(w2.x, s2.x, A2); A2 = ffma2(w2.y, s2.y, A2);
        }
        float Ov = hadd2(O2);
        sm.UAT[j][i] = B.Ub[i][j] - hadd2(A2);
        __syncthreads();

        // ---- phase C1: out = O + At @ UA (all 512 threads) ----
        {
            unsigned long long o2 = 0;
            #pragma unroll
            for (int f4 = 0; f4 < CHK; f4 += 4) {
                ulonglong2 a2v = *(const ulonglong2*)&B.Atb[i][f4];
                ulonglong2 u2v = *(const ulonglong2*)&sm.UAT[j][f4];
                o2 = ffma2(a2v.x, u2v.x, o2);
                o2 = ffma2(a2v.y, u2v.y, o2);
            }
            ob[(size_t)(ch * CHK + i) * DIM + j] = Ov + hadd2(o2);
        }

        // ---- phase C2: St[js][c0..3] += sum_r UA[r][js]*kn[r][c] (256 thr, 2 js) ----
        if (tid < 256) {
            const int js0 = jsg, js1 = jsg + 8;
            unsigned long long a0x = 0, a0y = 0, a1x = 0, a1y = 0;
            #pragma unroll 8
            for (int r = 0; r < CHK; r++) {
                unsigned long long u0 = pack2(sm.UAT[js0][r]);
                unsigned long long u1 = pack2(sm.UAT[js1][r]);
                ulonglong2 k2v = *(const ulonglong2*)&B.Kn[r][c0];
                a0x = ffma2(u0, k2v.x, a0x); a0y = ffma2(u0, k2v.y, a0y);
                a1x = ffma2(u1, k2v.x, a1x); a1y = ffma2(u1, k2v.y, a1y);
            }
            ulonglong2* p0 = (ulonglong2*)&sm.St[js0][c0];
            ulonglong2* p1 = (ulonglong2*)&sm.St[js1][c0];
            ulonglong2 v0 = *p0, v1 = *p1;
            v0.x = fadd2(v0.x, a0x); v0.y = fadd2(v0.y, a0y);
            v1.x = fadd2(v1.x, a1x); v1.y = fadd2(v1.y, a1y);
            *p0 = v0; *p1 = v1;
        }
        // loop-top barrier separates C2's St writes from next phase-A reads
    }

    if (write_s) {
        __syncthreads();
        float* sf = sfinal + (size_t)bh * DIM * DIM + sl * DV;
        for (int idx = tid; idx < DIM * DV; idx += THR2) {
            int c = idx >> 4, jv = idx & 15;
            sf[(size_t)c * DIM + jv] = sm.St[jv][c];
        }
    }
}

// ============================================================
extern "C" void kernel_launch(void* const* d_in, const int* in_sizes, int n_in,
                              void* d_out, int out_size) {
    const float* q    = (const float*)d_in[0];
    const float* k    = (const float*)d_in[1];
    const float* v    = (const float*)d_in[2];
    const float* beta = (const float*)d_in[3];
    float* out = (float*)d_out;

    const int out_elems = BH * LSEQ * DIM;
    const int s_elems   = BH * DIM * DIM;
    int write_s = (out_size >= out_elems + s_elems) ? 1 : 0;
    float* sf = out + out_elems;

    static bool attr_done = false;
    if (!attr_done) {
        cudaFuncSetAttribute(k1_prepare, cudaFuncAttributeMaxDynamicSharedMemorySize,
                             (int)sizeof(SM1));
        cudaFuncSetAttribute(k2_scan, cudaFuncAttributeMaxDynamicSharedMemorySize,
                             (int)sizeof(SM2));
        attr_done = true;
    }

    dim3 g1(NCHUNK, BH);
    k1_prepare<<<g1, 256, sizeof(SM1)>>>(q, k, v, beta);

    dim3 g2(BH, NSLICE);
    k2_scan<<<g2, THR2, sizeof(SM2)>>>(out, sf, write_s);
}